// round 16
// baseline (speedup 1.0000x reference)
#include <cuda_runtime.h>
#include <cuda_fp16.h>
#include <math.h>

#define NR 40000
#define NV 4000
#define ERR 400000
#define EVR 150000
#define ERV 150000
#define ET  (ERR+EVR+ERV)
#define FEA 128   // HEADS*H

// ---------------- scratch (device globals: allocation-free rule) ----------------
__device__ __half g_hs0[NR*FEA];
__device__ __half g_hs1[NV*FEA];
__device__ __half g_hs2[NR*FEA];
__device__ float g_accr[NR*FEA];
__device__ float g_accv[NV*FEA];
__device__ float g_es0[NR*2], g_es1[NV*2], g_es2[NR*2];
__device__ float g_ed0[NR*2], g_ed1[NR*2], g_ed2[NV*2];
__device__ int   g_off0[NR+1], g_off1[NR+1], g_off2[NV+1];
__device__ int   g_cur0[NR],   g_cur1[NR],   g_cur2[NV];
__device__ int   g_rank[ET];         // per-edge rank within dst bucket
__device__ int   g_srcs0[ERR], g_srcs1[EVR], g_srcs2[ERV];
__device__ float g_wdf[2*768];       // [layer][rel][head][k]
__device__ float g_M[48], g_Mc[6];   // folded edge-attr head
__device__ float g_bns[2*512];       // BN sums per layer: [req s][req sq][veh s][veh sq]
__device__ float g_prs[NR*2], g_prd[NR*2], g_pvs[NV*2], g_pvd[NV*2];
__device__ float2 g_eaM[ET];         // precomputed per-edge ea@M + Mc

__device__ __forceinline__ float lrelu(float x){ return x >= 0.f ? x : 0.2f*x; }
__device__ __forceinline__ float cleanf(float x){
  if(isnan(x)) return 0.f;
  if(isinf(x)) return x>0.f ? 3.402823466e38f : -3.402823466e38f;
  return x;
}

// packed f32x2 helpers (B300: 2x fp32 FMA throughput, PTX-only)
#define PACK_DUP(out, f) asm("mov.b64 %0, {%1, %1};" : "=l"(out) : "r"(__float_as_uint(f)))
#define FMA2(d, a, b, c) asm("fma.rn.f32x2 %0, %1, %2, %3;" : "=l"(d) : "l"(a), "l"(b), "l"(c))
#define UNPACK2(lo, hi, in) asm("mov.b64 {%0, %1}, %2;" : "=f"(lo), "=f"(hi) : "l"(in))

// BN fold: (s1,s2) for feature f of node-type `type` from raw sums
__device__ __forceinline__ void bn_fold1(const float* __restrict__ bns,
                                         const float* __restrict__ gam,
                                         const float* __restrict__ bet,
                                         int type, int goff, int f,
                                         float& s1, float& s2){
  float Nn   = type? (float)NV : (float)NR;
  float scale= type? 1.f : 0.5f;
  int base=type*256;
  float invN=1.f/Nn;
  float mu = bns[base+f]*invN;
  float var= bns[base+128+f]*invN - mu*mu;
  float rs = rsqrtf(var+1e-5f);
  float g=__ldg(&gam[goff+type*128+f]), b=__ldg(&bet[goff+type*128+f]);
  s1=scale*rs*g;
  s2=b-mu*rs*g;
}

// ---------------- setup (main stream): zero bns + counters + wdf + folded edge head -------------
#define ZB ((2*NR+NV+255)/256)
__global__ void k_setup_main(float* __restrict__ bns,
                        int* __restrict__ c0,int* __restrict__ c1,int* __restrict__ c2,
                        const float* __restrict__ Wd1,const float* __restrict__ ad1,
                        const float* __restrict__ Wd2,const float* __restrict__ ad2,
                        const float* __restrict__ Wp,const float* __restrict__ bp,
                        const float* __restrict__ Wlin,const float* __restrict__ blin,
                        float* __restrict__ wdf, float* __restrict__ M, float* __restrict__ Mc){
  int b=blockIdx.x;
  if(b>=4){
    int i=(b-4)*256+threadIdx.x;
    if(i<NR) c0[i]=0;
    else if(i<2*NR) c1[i-NR]=0;
    else if(i<2*NR+NV) c2[i-2*NR]=0;
    return;
  }
  int t=b*256+threadIdx.x;   // 0..1023
  bns[t]=0.f;
  if(t<96){
    int rel=t/32, rem=t%32, h=rem/16, k=rem%16;
    const float* w=Wd1+(size_t)rel*16*128 + k*128 + h*64;
    const float* a=ad1+rel*128+h*64;
    float s=0.f; for(int j=0;j<64;j++) s+=w[j]*a[j];
    wdf[rel*256+h*128+k]=s;
  } else if(t<864){
    int i=t-96; int rel=i/256, rem=i%256, h=rem/128, k=rem%128;
    const float* w=Wd2+(size_t)rel*128*128 + k*128 + h*64;
    const float* a=ad2+rel*128+h*64;
    float s=0.f; for(int j=0;j<64;j++) s+=w[j]*a[j];
    wdf[768+rel*256+h*128+k]=s;
  } else if(t<912){
    int q=t-864; int rel=q>>4, rem=q&15, k=rem>>1, o=rem&1;
    float s=0.f;
    for(int j=0;j<64;j++) s+=Wp[rel*512+k*64+j]*Wlin[(128+j)*2+o];
    M[q]=s;
  } else if(t<918){
    int i=t-912, rel=i>>1, o=i&1;
    float s=blin[o];
    for(int j=0;j<64;j++) s+=bp[rel*64+j]*Wlin[(128+j)*2+o];
    Mc[i]=s;
  }
}

// ---------------- side-stream CSR build: count (stores rank) -> scan -> atomic-free fill --------
__global__ void k_count3(const int* __restrict__ d0,const int* __restrict__ d1,const int* __restrict__ d2,
                         int* __restrict__ c0,int* __restrict__ c1,int* __restrict__ c2,
                         int* __restrict__ rank){
  int t=blockIdx.x*blockDim.x+threadIdx.x;
  const int Q0=ERR/4, Q1=EVR/4, Q2=ERV/4;
  int4 r;
  if(t<Q0){
    int4 d=((const int4*)d0)[t];
    r.x=atomicAdd(&c0[d.x],1); r.y=atomicAdd(&c0[d.y],1);
    r.z=atomicAdd(&c0[d.z],1); r.w=atomicAdd(&c0[d.w],1);
    ((int4*)rank)[t]=r;
  } else if(t<Q0+Q1){
    int4 d=((const int4*)d1)[t-Q0];
    r.x=atomicAdd(&c1[d.x],1); r.y=atomicAdd(&c1[d.y],1);
    r.z=atomicAdd(&c1[d.z],1); r.w=atomicAdd(&c1[d.w],1);
    ((int4*)rank)[t]=r;
  } else if(t<Q0+Q1+Q2){
    int4 d=((const int4*)d2)[t-Q0-Q1];
    r.x=atomicAdd(&c2[d.x],1); r.y=atomicAdd(&c2[d.y],1);
    r.z=atomicAdd(&c2[d.z],1); r.w=atomicAdd(&c2[d.w],1);
    ((int4*)rank)[t]=r;
  }
}
__global__ void k_scan3(const int* __restrict__ c0,int* __restrict__ o0,
                        const int* __restrict__ c1,int* __restrict__ o1,
                        const int* __restrict__ c2,int* __restrict__ o2){
  __shared__ int part[1024];
  const int* cnt; int* off; int n;
  if(blockIdx.x==0){cnt=c0;off=o0;n=NR;}
  else if(blockIdx.x==1){cnt=c1;off=o1;n=NR;}
  else {cnt=c2;off=o2;n=NV;}
  int t=threadIdx.x;
  int chunk=(n+1023)>>10;
  int lo=t*chunk, hi=min(n, lo+chunk);
  int s=0;
  for(int i=lo;i<hi;i++) s+=cnt[i];
  part[t]=s;
  __syncthreads();
  for(int d=1;d<1024;d<<=1){
    int v=(t>=d)? part[t-d]:0;
    __syncthreads();
    if(t>=d) part[t]+=v;
    __syncthreads();
  }
  int base=(t==0)?0:part[t-1];
  for(int i=lo;i<hi;i++){ int c=cnt[i]; off[i]=base; base+=c; }
  if(t==1023) off[n]=part[1023];
}
__global__ void k_fill3(const int* __restrict__ rr,const int* __restrict__ vr,const int* __restrict__ rv,
                        const int* __restrict__ o0,const int* __restrict__ o1,const int* __restrict__ o2,
                        const int* __restrict__ rank,
                        int* __restrict__ s0,int* __restrict__ s1,int* __restrict__ s2){
  int t=blockIdx.x*blockDim.x+threadIdx.x;
  const int Q0=ERR/4, Q1=EVR/4, Q2=ERV/4;
  if(t<Q0){
    int4 sr=((const int4*)rr)[t];
    int4 ds=((const int4*)(rr+ERR))[t];
    int4 rk=((const int4*)rank)[t];
    s0[__ldg(&o0[ds.x])+rk.x]=sr.x;
    s0[__ldg(&o0[ds.y])+rk.y]=sr.y;
    s0[__ldg(&o0[ds.z])+rk.z]=sr.z;
    s0[__ldg(&o0[ds.w])+rk.w]=sr.w;
  } else if(t<Q0+Q1){
    int i=t-Q0;
    int4 sr=((const int4*)vr)[i];
    int4 ds=((const int4*)(vr+EVR))[i];
    int4 rk=((const int4*)rank)[t];
    s1[__ldg(&o1[ds.x])+rk.x]=sr.x;
    s1[__ldg(&o1[ds.y])+rk.y]=sr.y;
    s1[__ldg(&o1[ds.z])+rk.z]=sr.z;
    s1[__ldg(&o1[ds.w])+rk.w]=sr.w;
  } else if(t<Q0+Q1+Q2){
    int i=t-Q0-Q1;
    int4 sr=((const int4*)rv)[i];
    int4 ds=((const int4*)(rv+ERV))[i];
    int4 rk=((const int4*)rank)[t];
    s2[__ldg(&o2[ds.x])+rk.x]=sr.x;
    s2[__ldg(&o2[ds.y])+rk.y]=sr.y;
    s2[__ldg(&o2[ds.z])+rk.z]=sr.z;
    s2[__ldg(&o2[ds.w])+rk.w]=sr.w;
  }
}

// ---------------- per-edge attr projection: eaM[e] = ea[e]@M + Mc (main stream, idle window) ----
__device__ __forceinline__ void eaM4(const float* __restrict__ ea, int i4,
                                     const float* __restrict__ M, const float* __restrict__ Mc,
                                     float2* __restrict__ eaM, int obase){
  float mm[16];
  #pragma unroll
  for(int k=0;k<16;k++) mm[k]=__ldg(&M[k]);
  float c0=__ldg(&Mc[0]), c1=__ldg(&Mc[1]);
  #pragma unroll
  for(int q=0;q<4;q++){
    int e=i4*4+q;
    float4 a0=__ldg((const float4*)(ea+(size_t)e*8));
    float4 a1=__ldg((const float4*)(ea+(size_t)e*8)+1);
    float av[8]={a0.x,a0.y,a0.z,a0.w,a1.x,a1.y,a1.z,a1.w};
    float l0=c0, l1=c1;
    #pragma unroll
    for(int k=0;k<8;k++){
      float a=cleanf(av[k]);
      l0+=a*mm[k*2]; l1+=a*mm[k*2+1];
    }
    eaM[obase+e]=make_float2(l0,l1);
  }
}
__global__ void k_eaM(const float* __restrict__ ea_rr, const float* __restrict__ ea_vr,
                      const float* __restrict__ ea_rv,
                      const float* __restrict__ M, const float* __restrict__ Mc,
                      float2* __restrict__ eaM){
  int t=blockIdx.x*blockDim.x+threadIdx.x;
  const int Q0=ERR/4, Q1=EVR/4, Q2=ERV/4;
  if(t<Q0)            eaM4(ea_rr,t,      M,   Mc,  eaM,0);
  else if(t<Q0+Q1)    eaM4(ea_vr,t-Q0,   M+16,Mc+2,eaM,ERR);
  else if(t<Q0+Q1+Q2) eaM4(ea_rv,t-Q0-Q1,M+32,Mc+4,eaM,ERR+EVR);
}

// ---------------- GEMM (f32x2): 3 relations/launch; fused es + ed; staged BN(inline fold)/clean --
template<int K, int MODE>
__global__ void k_gemm3(const float* __restrict__ Ar, const float* __restrict__ Av,
                        const float* __restrict__ W,
                        __half* __restrict__ hs0, __half* __restrict__ hs1, __half* __restrict__ hs2,
                        const float* __restrict__ as,
                        float* __restrict__ es0, float* __restrict__ es1, float* __restrict__ es2,
                        const float* __restrict__ wdf,
                        float* __restrict__ ed0, float* __restrict__ ed1, float* __restrict__ ed2,
                        const float* __restrict__ bns,
                        const float* __restrict__ gam, const float* __restrict__ bet){
  constexpr int CH = (K<32)?K:32;
  constexpr int NI = (K+31)/32;
  __shared__ float Wsh[CH*128];
  __shared__ float Ash[64*K];
  int t=threadIdx.x, warp=t>>5, lane=t&31;
  int rel=blockIdx.y;
  const float* A; __half* C; float* es; int N;
  const float* wd0=nullptr; const float* wd1=nullptr;
  float* edA=nullptr; float* edB=nullptr;
  if(rel==0){A=Ar;C=hs0;es=es0;N=NR;wd0=wdf;wd1=wdf+256;edA=ed0;edB=ed1;}
  else if(rel==1){A=Av;C=hs1;es=es1;N=NV;wd0=wdf+512;edA=ed2;}
  else {A=Ar;C=hs2;es=es2;N=NR;}
  int row0=blockIdx.x*64;
  if(row0>=N) return;
  const float* Wr = W + (size_t)rel*K*128;

  float b1[4]={0,0,0,0}, b2[4]={0,0,0,0};
  if(MODE==1){
    int type=(rel==1)?1:0;
    int fb=(t%(K/4))*4;
    #pragma unroll
    for(int q=0;q<4;q++) bn_fold1(bns,gam,bet,type,0,fb+q,b1[q],b2[q]);
  }

  for(int i=t;i<64*(K/4);i+=256){
    int r=i/(K/4), c=i%(K/4);
    if(row0+r<N){
      float4 v=((const float4*)(A+(size_t)(row0+r)*K))[c];
      if(MODE==0){v.x=cleanf(v.x);v.y=cleanf(v.y);v.z=cleanf(v.z);v.w=cleanf(v.w);}
      else {
        v.x=lrelu(v.x*b1[0]+b2[0]); v.y=lrelu(v.y*b1[1]+b2[1]);
        v.z=lrelu(v.z*b1[2]+b2[2]); v.w=lrelu(v.w*b1[3]+b2[3]);
      }
      ((float4*)Ash)[i]=v;
    }
  }

  unsigned long long acc[8][2];
  #pragma unroll
  for(int r=0;r<8;r++){acc[r][0]=0ull;acc[r][1]=0ull;}

  for(int kc=0;kc<K;kc+=CH){
    __syncthreads();
    {
      const float4* Wg=(const float4*)(Wr+(size_t)kc*128);
      float4* Ws4=(float4*)Wsh;
      for(int i=t;i<CH*32;i+=256) Ws4[i]=Wg[i];
    }
    __syncthreads();
    const ulonglong2* W2=(const ulonglong2*)Wsh;
    #pragma unroll
    for(int k4=0;k4<CH/4;k4++){
      ulonglong2 w0=W2[(k4*4+0)*32+lane];
      ulonglong2 w1=W2[(k4*4+1)*32+lane];
      ulonglong2 w2=W2[(k4*4+2)*32+lane];
      ulonglong2 w3=W2[(k4*4+3)*32+lane];
      #pragma unroll
      for(int r=0;r<8;r++){
        float4 a=*(const float4*)(Ash + (warp*8+r)*K + kc + k4*4);
        unsigned long long ax,ay,az,aw;
        PACK_DUP(ax,a.x); PACK_DUP(ay,a.y); PACK_DUP(az,a.z); PACK_DUP(aw,a.w);
        FMA2(acc[r][0],ax,w0.x,acc[r][0]); FMA2(acc[r][1],ax,w0.y,acc[r][1]);
        FMA2(acc[r][0],ay,w1.x,acc[r][0]); FMA2(acc[r][1],ay,w1.y,acc[r][1]);
        FMA2(acc[r][0],az,w2.x,acc[r][0]); FMA2(acc[r][1],az,w2.y,acc[r][1]);
        FMA2(acc[r][0],aw,w3.x,acc[r][0]); FMA2(acc[r][1],aw,w3.y,acc[r][1]);
      }
    }
  }

  float4 av=__ldg((const float4*)(as+rel*128)+lane);
  float wA0[NI],wA1[NI],wB0[NI],wB1[NI];
  if(edA){
    #pragma unroll
    for(int i=0;i<NI;i++){
      int k=lane+32*i;
      wA0[i]=(k<K)?__ldg(&wd0[k]):0.f;
      wA1[i]=(k<K)?__ldg(&wd0[128+k]):0.f;
      if(edB){ wB0[i]=(k<K)?__ldg(&wd1[k]):0.f; wB1[i]=(k<K)?__ldg(&wd1[128+k]):0.f; }
    }
  }
  #pragma unroll
  for(int r=0;r<8;r++){
    int row=row0+warp*8+r;
    if(row>=N) continue;
    float4 o;
    UNPACK2(o.x,o.y,acc[r][0]);
    UNPACK2(o.z,o.w,acc[r][1]);
    union { __half2 h[2]; uint2 u; } cv;
    cv.h[0]=__floats2half2_rn(o.x,o.y);
    cv.h[1]=__floats2half2_rn(o.z,o.w);
    ((uint2*)C)[row*32+lane]=cv.u;
    float s=o.x*av.x+o.y*av.y+o.z*av.z+o.w*av.w;
    #pragma unroll
    for(int off=8;off>=1;off>>=1) s+=__shfl_xor_sync(0xffffffffu,s,off,16);
    if(lane==0)  es[row*2]=s;
    if(lane==16) es[row*2+1]=s;
    if(edA){
      float s0=0.f,s1=0.f,s2=0.f,s3=0.f;
      #pragma unroll
      for(int i=0;i<NI;i++){
        int k=lane+32*i;
        if(k<K){
          float xv=Ash[(warp*8+r)*K+k];
          s0+=xv*wA0[i]; s1+=xv*wA1[i];
          if(edB){ s2+=xv*wB0[i]; s3+=xv*wB1[i]; }
        }
      }
      #pragma unroll
      for(int off=16;off>=1;off>>=1){
        s0+=__shfl_xor_sync(0xffffffffu,s0,off);
        s1+=__shfl_xor_sync(0xffffffffu,s1,off);
        if(edB){ s2+=__shfl_xor_sync(0xffffffffu,s2,off); s3+=__shfl_xor_sync(0xffffffffu,s3,off); }
      }
      if(lane==0){
        edA[row*2]=s0; edA[row*2+1]=s1;
        if(edB){ edB[row*2]=s2; edB[row*2+1]=s3; }
      }
    }
  }
}

// ---------------- softmax-aggregate one relation for node w (warp-collective, fp16 hs) ----------
__device__ __forceinline__ float4 hgather(const __half* __restrict__ hs, int sj, int lane){
  uint2 hv=__ldg((const uint2*)hs + (size_t)sj*32 + lane);
  __half2 a01=*(__half2*)&hv.x, a23=*(__half2*)&hv.y;
  float2 f01=__half22float2(a01), f23=__half22float2(a23);
  return make_float4(f01.x,f01.y,f23.x,f23.y);
}

__device__ __forceinline__ float4 agg_rel(
    const int* __restrict__ off, const int* __restrict__ srcs,
    const float* __restrict__ es, const float* __restrict__ ed,
    const __half* __restrict__ hs, int w, int lane, bool h1)
{
  float4 acc=make_float4(0.f,0.f,0.f,0.f);
  int a0=off[w], deg=off[w+1]-a0;
  if(deg==0) return acc;
  float ed0=ed[w*2], ed1=ed[w*2+1];
  if(deg<=128){
    int nc=(deg+31)>>5;
    int   sreg[4];
    float e0[4], e1[4];
    float m0=-1e30f, m1=-1e30f;
    #pragma unroll
    for(int c=0;c<4;c++){
      e0[c]=-1e30f; e1[c]=-1e30f; sreg[c]=0;
      if(c<nc){
        int i=c*32+lane;
        if(i<deg){
          int s=__ldg(&srcs[a0+i]); sreg[c]=s;
          float2 ev=__ldg((const float2*)(es)+s);
          e0[c]=lrelu(ev.x+ed0); e1[c]=lrelu(ev.y+ed1);
          m0=fmaxf(m0,e0[c]); m1=fmaxf(m1,e1[c]);
        }
      }
    }
    #pragma unroll
    for(int o=16;o>=1;o>>=1){
      m0=fmaxf(m0,__shfl_xor_sync(0xffffffffu,m0,o));
      m1=fmaxf(m1,__shfl_xor_sync(0xffffffffu,m1,o));
    }
    float s0=0.f, s1=0.f;
    #pragma unroll
    for(int c=0;c<4;c++){
      e0[c]=__expf(e0[c]-m0);
      e1[c]=__expf(e1[c]-m1);
      s0+=e0[c]; s1+=e1[c];
    }
    #pragma unroll
    for(int o=16;o>=1;o>>=1){
      s0+=__shfl_xor_sync(0xffffffffu,s0,o);
      s1+=__shfl_xor_sync(0xffffffffu,s1,o);
    }
    float inv=1.f/(h1?s1:s0);
    #pragma unroll
    for(int c=0;c<4;c++){
      if(c>=nc) break;
      int n=min(32,deg-c*32);
      for(int j=0;j<n;j++){
        int   sj=__shfl_sync(0xffffffffu,sreg[c],j);
        float aa=__shfl_sync(0xffffffffu,e0[c],j);
        float ab=__shfl_sync(0xffffffffu,e1[c],j);
        float al=(h1?ab:aa)*inv;
        float4 h=hgather(hs,sj,lane);
        acc.x+=h.x*al; acc.y+=h.y*al; acc.z+=h.z*al; acc.w+=h.w*al;
      }
    }
  } else {
    float m0=-1e30f, m1=-1e30f;
    for(int i=lane;i<deg;i+=32){
      int s=__ldg(&srcs[a0+i]);
      float2 ev=__ldg((const float2*)(es)+s);
      m0=fmaxf(m0,lrelu(ev.x+ed0)); m1=fmaxf(m1,lrelu(ev.y+ed1));
    }
    for(int o=16;o>=1;o>>=1){
      m0=fmaxf(m0,__shfl_xor_sync(0xffffffffu,m0,o));
      m1=fmaxf(m1,__shfl_xor_sync(0xffffffffu,m1,o));
    }
    float s0=0.f, s1=0.f;
    for(int i=lane;i<deg;i+=32){
      int s=__ldg(&srcs[a0+i]);
      float2 ev=__ldg((const float2*)(es)+s);
      s0+=__expf(lrelu(ev.x+ed0)-m0);
      s1+=__expf(lrelu(ev.y+ed1)-m1);
    }
    for(int o=16;o>=1;o>>=1){
      s0+=__shfl_xor_sync(0xffffffffu,s0,o);
      s1+=__shfl_xor_sync(0xffffffffu,s1,o);
    }
    float inv=1.f/(h1?s1:s0);
    for(int base=0;base<deg;base+=32){
      int n=min(32,deg-base);
      int sv=0; float ev0=0.f, ev1=0.f;
      if(lane<n){
        sv=__ldg(&srcs[a0+base+lane]);
        float2 ev=__ldg((const float2*)(es)+sv);
        ev0=__expf(lrelu(ev.x+ed0)-m0);
        ev1=__expf(lrelu(ev.y+ed1)-m1);
      }
      for(int j=0;j<n;j++){
        int   sj=__shfl_sync(0xffffffffu,sv,j);
        float aa=__shfl_sync(0xffffffffu,ev0,j);
        float ab=__shfl_sync(0xffffffffu,ev1,j);
        float al=(h1?ab:aa)*inv;
        float4 h=hgather(hs,sj,lane);
        acc.x+=h.x*al; acc.y+=h.y*al; acc.z+=h.z*al; acc.w+=h.w*al;
      }
    }
  }
  return acc;
}

// agg + bias + fused BN statistics. 1 node/warp; 64-thread blocks (2 nodes) for
// finest load balance. veh blocks first (3x longer).
__global__ void k_agg_all(const int* __restrict__ off0,const int* __restrict__ s0,
                          const float* __restrict__ es0,const float* __restrict__ ed0,
                          const __half* __restrict__ hs0,
                          const int* __restrict__ off1,const int* __restrict__ s1,
                          const float* __restrict__ es1,const float* __restrict__ ed1,
                          const __half* __restrict__ hs1,
                          const int* __restrict__ off2,const int* __restrict__ s2,
                          const float* __restrict__ es2,const float* __restrict__ ed2,
                          const __half* __restrict__ hs2,
                          const float* __restrict__ bs,
                          float* __restrict__ accr, float* __restrict__ accv,
                          float* __restrict__ bns){
  __shared__ float s_sum[128], s_sq[128];
  int t=threadIdx.x, warp=t>>5, lane=t&31;
  bool h1=lane>=16;
  s_sum[t]=0.f; s_sum[t+64]=0.f; s_sq[t]=0.f; s_sq[t+64]=0.f;
  __syncthreads();
  bool isveh = blockIdx.x<(NV/2);
  float4 v;
  if(isveh){
    int w=blockIdx.x*2+warp;
    float4 b0=__ldg((const float4*)(bs+256)+lane);
    float4 a=agg_rel(off2,s2,es2,ed2,hs2,w,lane,h1);
    float4 o;
    o.x=b0.x+a.x; o.y=b0.y+a.y; o.z=b0.z+a.z; o.w=b0.w+a.w;
    ((float4*)(accv+(size_t)w*128))[lane]=o;
    v=o;
  } else {
    int w=(blockIdx.x-(NV/2))*2+warp;
    float4 b0=__ldg((const float4*)bs+lane);
    float4 b1=__ldg((const float4*)(bs+128)+lane);
    float4 a=agg_rel(off0,s0,es0,ed0,hs0,w,lane,h1);
    float4 b=agg_rel(off1,s1,es1,ed1,hs1,w,lane,h1);
    float4 o;
    o.x=b0.x+b1.x+a.x+b.x; o.y=b0.y+b1.y+a.y+b.y;
    o.z=b0.z+b1.z+a.z+b.z; o.w=b0.w+b1.w+a.w+b.w;
    ((float4*)(accr+(size_t)w*128))[lane]=o;
    v.x=0.5f*o.x; v.y=0.5f*o.y; v.z=0.5f*o.z; v.w=0.5f*o.w;
  }
  int f=lane*4;
  atomicAdd(&s_sum[f+0],v.x); atomicAdd(&s_sum[f+1],v.y);
  atomicAdd(&s_sum[f+2],v.z); atomicAdd(&s_sum[f+3],v.w);
  atomicAdd(&s_sq[f+0],v.x*v.x); atomicAdd(&s_sq[f+1],v.y*v.y);
  atomicAdd(&s_sq[f+2],v.z*v.z); atomicAdd(&s_sq[f+3],v.w*v.w);
  __syncthreads();
  int base=isveh?256:0;
  atomicAdd(&bns[base+t],      s_sum[t]);
  atomicAdd(&bns[base+t+64],   s_sum[t+64]);
  atomicAdd(&bns[base+128+t],    s_sq[t]);
  atomicAdd(&bns[base+128+t+64], s_sq[t+64]);
}

// ---------------- final head: node projections (inline layer-2 BN fold) ----------------
__global__ void k_proj4(const float* __restrict__ accr, const float* __restrict__ accv,
                        const float* __restrict__ bns,
                        const float* __restrict__ gam, const float* __restrict__ bet,
                        const float* __restrict__ Wlin,
                        float* __restrict__ prs, float* __restrict__ prd,
                        float* __restrict__ pvs, float* __restrict__ pvd){
  int gid=blockIdx.x*blockDim.x+threadIdx.x;
  int w=gid>>5, lane=gid&31;
  const float* X; float* P; int base; int idx; int type;
  if(w<NR){X=accr;P=prs;base=0;idx=w;type=0;}
  else if(w<2*NR){X=accr;P=prd;base=192;idx=w-NR;type=0;}
  else if(w<2*NR+NV){X=accv;P=pvs;base=0;idx=w-2*NR;type=1;}
  else if(w<2*NR+2*NV){X=accv;P=pvd;base=192;idx=w-2*NR-NV;type=1;}
  else return;
  float4 x=__ldg((const float4*)(X+(size_t)idx*FEA)+lane);
  float s1[4],s2[4];
  #pragma unroll
  for(int q=0;q<4;q++) bn_fold1(bns,gam,bet,type,256,lane*4+q,s1[q],s2[q]);
  x.x=lrelu(x.x*s1[0]+s2[0]); x.y=lrelu(x.y*s1[1]+s2[1]);
  x.z=lrelu(x.z*s1[2]+s2[2]); x.w=lrelu(x.w*s1[3]+s2[3]);
  const float* wr=Wlin+(base+lane*4)*2;
  float4 wa=__ldg((const float4*)wr);
  float4 wb=__ldg((const float4*)wr+1);
  float p0=x.x*wa.x + x.y*wa.z + x.z*wb.x + x.w*wb.z;
  float p1=x.x*wa.y + x.y*wa.w + x.z*wb.y + x.w*wb.w;
  for(int o=16;o>=1;o>>=1){
    p0+=__shfl_xor_sync(0xffffffffu,p0,o);
    p1+=__shfl_xor_sync(0xffffffffu,p1,o);
  }
  if(lane==0){ P[idx*2]=p0; P[idx*2+1]=p1; }
}

// ---------------- per-edge output (4 edges/thread; uses precomputed eaM) ----------------
__device__ __forceinline__ void edge4(const int* __restrict__ ei, int E, int i4,
                                      const float* __restrict__ ps, const float* __restrict__ pd,
                                      const float2* __restrict__ eaM,
                                      float* __restrict__ out, int obase){
  int4 sr=((const int4*)ei)[i4];
  int4 ds=((const int4*)(ei+E))[i4];
  int ss[4]={sr.x,sr.y,sr.z,sr.w};
  int dd[4]={ds.x,ds.y,ds.z,ds.w};
  float2 pse[4], pde[4], em[4];
  #pragma unroll
  for(int q=0;q<4;q++){
    pse[q]=__ldg((const float2*)ps+ss[q]);
    pde[q]=__ldg((const float2*)pd+dd[q]);
    em[q]=__ldg(&eaM[obase+i4*4+q]);
  }
  #pragma unroll
  for(int q=0;q<4;q++){
    int e=i4*4+q;
    float l0=pse[q].x+pde[q].x+em[q].x;
    float l1=pse[q].y+pde[q].y+em[q].y;
    float mx=fmaxf(l0,l1);
    float e0=__expf(l0-mx), e1=__expf(l1-mx);
    float inv=1.f/(e0+e1);
    out[(size_t)(obase+e)*2]=e0*inv; out[(size_t)(obase+e)*2+1]=e1*inv;
  }
}

__global__ void k_edgeout_all(const int* __restrict__ ei_rr,
                              const int* __restrict__ ei_vr,
                              const int* __restrict__ ei_rv,
                              const float* __restrict__ prs, const float* __restrict__ prd,
                              const float* __restrict__ pvs, const float* __restrict__ pvd,
                              const float2* __restrict__ eaM,
                              float* __restrict__ out){
  int t=blockIdx.x*blockDim.x+threadIdx.x;
  const int Q0=ERR/4, Q1=EVR/4, Q2=ERV/4;
  if(t<Q0)            edge4(ei_rr,ERR,t,      prs,prd,eaM,out,0);
  else if(t<Q0+Q1)    edge4(ei_vr,EVR,t-Q0,   pvs,prd,eaM,out,ERR);
  else if(t<Q0+Q1+Q2) edge4(ei_rv,ERV,t-Q0-Q1,prs,pvd,eaM,out,ERR+EVR);
}

// ---------------- host ----------------
#define SYM(var, sym) do{ void* _p; cudaGetSymbolAddress(&_p, sym); var=(decltype(var))_p; }while(0)

extern "C" void kernel_launch(void* const* d_in, const int* in_sizes, int n_in,
                              void* d_out, int out_size){
  (void)in_sizes; (void)n_in; (void)out_size;
  const float* x_req=(const float*)d_in[0];
  const float* x_veh=(const float*)d_in[1];
  const int*   ei_rr=(const int*)d_in[2];
  const int*   ei_vr=(const int*)d_in[3];
  const int*   ei_rv=(const int*)d_in[4];
  const float* ea_rr=(const float*)d_in[5];
  const float* ea_vr=(const float*)d_in[6];
  const float* ea_rv=(const float*)d_in[7];
  const float* Wsrc1=(const float*)d_in[8];
  const float* Wdst1=(const float*)d_in[9];
  const float* asrc1=(const float*)d_in[10];
  const float* adst1=(const float*)d_in[11];
  const float* bias1=(const float*)d_in[12];
  const float* Wsrc2=(const float*)d_in[13];
  const float* Wdst2=(const float*)d_in[14];
  const float* asrc2=(const float*)d_in[15];
  const float* adst2=(const float*)d_in[16];
  const float* bias2=(const float*)d_in[17];
  const float* bn_gamma=(const float*)d_in[18];
  const float* bn_beta =(const float*)d_in[19];
  const float* Wp  =(const float*)d_in[20];
  const float* bp  =(const float*)d_in[21];
  const float* Wlin=(const float*)d_in[22];
  const float* blin=(const float*)d_in[23];
  float* out=(float*)d_out;

  __half *hs0,*hs1,*hs2;
  float *accr,*accv;
  float *es0,*es1,*es2,*ed0,*ed1,*ed2,*wdf,*M,*Mc,*bns,*prs,*prd,*pvs,*pvd;
  float2 *eaM;
  int *off0,*off1,*off2,*cur0,*cur1,*cur2,*srcs0,*srcs1,*srcs2,*rank;
  SYM(hs0,g_hs0); SYM(hs1,g_hs1); SYM(hs2,g_hs2);
  SYM(accr,g_accr); SYM(accv,g_accv);
  SYM(es0,g_es0); SYM(es1,g_es1); SYM(es2,g_es2);
  SYM(ed0,g_ed0); SYM(ed1,g_ed1); SYM(ed2,g_ed2);
  SYM(off0,g_off0); SYM(off1,g_off1); SYM(off2,g_off2);
  SYM(cur0,g_cur0); SYM(cur1,g_cur1); SYM(cur2,g_cur2);
  SYM(srcs0,g_srcs0); SYM(srcs1,g_srcs1); SYM(srcs2,g_srcs2); SYM(rank,g_rank);
  SYM(wdf,g_wdf); SYM(M,g_M); SYM(Mc,g_Mc); SYM(bns,g_bns);
  SYM(prs,g_prs); SYM(prd,g_prd); SYM(pvs,g_pvs); SYM(pvd,g_pvd);
  SYM(eaM,g_eaM);

  // fork a side stream for the CSR build (graph-capturable event fork/join).
  // stream/event objects are host-side; intentionally not destroyed (capture
  // forbids destroying in-capture streams; kernel_launch runs O(1) times).
  cudaStream_t sidest;
  cudaEvent_t evSetup, evJoin;
  cudaStreamCreateWithFlags(&sidest, cudaStreamNonBlocking);
  cudaEventCreateWithFlags(&evSetup, cudaEventDisableTiming);
  cudaEventCreateWithFlags(&evJoin, cudaEventDisableTiming);

  // ---- main stream: setup (zeros counters + bns, computes wdf/M/Mc) ----
  k_setup_main<<<4+ZB,256>>>(bns,cur0,cur1,cur2,Wdst1,adst1,Wdst2,adst2,
                             Wp,bp,Wlin,blin,wdf,M,Mc);
  cudaEventRecord(evSetup, 0);

  // ---- side stream: CSR build (count stores rank; fill atomic-free) ----
  cudaStreamWaitEvent(sidest, evSetup, 0);
  k_count3<<<(ET/4+255)/256,256,0,sidest>>>(ei_rr+ERR,ei_vr+EVR,ei_rv+ERV,
                                            cur0,cur1,cur2,rank);
  k_scan3<<<3,1024,0,sidest>>>(cur0,off0,cur1,off1,cur2,off2);
  k_fill3<<<(ET/4+255)/256,256,0,sidest>>>(ei_rr,ei_vr,ei_rv,off0,off1,off2,rank,
                                           srcs0,srcs1,srcs2);
  cudaEventRecord(evJoin, sidest);

  // ---- main stream: gemm L0 + eaM precompute (independent of CSR) ----
  {
    dim3 grid((NR+63)/64,3);
    k_gemm3<16,0><<<grid,256>>>(x_req,x_veh,Wsrc1,hs0,hs1,hs2,asrc1,es0,es1,es2,
                                wdf,ed0,ed1,ed2,nullptr,nullptr,nullptr);
  }
  k_eaM<<<(ET/4+255)/256,256>>>(ea_rr,ea_vr,ea_rv,M,Mc,eaM);

  // join: agg needs CSR + gemm outputs
  cudaStreamWaitEvent(0, evJoin, 0);

  // ---- layer 0 agg ----
  k_agg_all<<<NR/2+NV/2,64>>>(off0,srcs0,es0,ed0,hs0, off1,srcs1,es1,ed1,hs1,
                              off2,srcs2,es2,ed2,hs2, bias1,accr,accv,bns);
  // ---- layer 1 (BN-0 fold inlined into A staging) ----
  {
    dim3 grid((NR+63)/64,3);
    k_gemm3<128,1><<<grid,256>>>(accr,accv,Wsrc2,hs0,hs1,hs2,asrc2,es0,es1,es2,
                                 wdf+768,ed0,ed1,ed2,bns,bn_gamma,bn_beta);
  }
  k_agg_all<<<NR/2+NV/2,64>>>(off0,srcs0,es0,ed0,hs0, off1,srcs1,es1,ed1,hs1,
                              off2,srcs2,es2,ed2,hs2, bias2,accr,accv,bns+512);

  // ---- final per-edge head (BN-1 fold inlined into proj; edgeout uses eaM) ----
  k_proj4<<<((2*NR+2*NV)*32+255)/256,256>>>(accr,accv,bns+512,bn_gamma,bn_beta,
                                            Wlin,prs,prd,pvs,pvd);
  k_edgeout_all<<<(ET/4+255)/256,256>>>(ei_rr,ei_vr,ei_rv,
                                        prs,prd,pvs,pvd,eaM,out);
}

// round 17
// speedup vs baseline: 1.2395x; 1.2395x over previous
#include <cuda_runtime.h>
#include <cuda_fp16.h>
#include <math.h>

#define NR 40000
#define NV 4000
#define ERR 400000
#define EVR 150000
#define ERV 150000
#define ET  (ERR+EVR+ERV)
#define FEA 128   // HEADS*H

// ---------------- scratch (device globals: allocation-free rule) ----------------
__device__ __half g_hs0[NR*FEA];
__device__ __half g_hs1[NV*FEA];
__device__ __half g_hs2[NR*FEA];
__device__ float g_accr[NR*FEA];
__device__ float g_accv[NV*FEA];
__device__ float g_es0[NR*2], g_es1[NV*2], g_es2[NR*2];
__device__ float g_ed0[NR*2], g_ed1[NR*2], g_ed2[NV*2];
__device__ int   g_off0[NR+1], g_off1[NR+1], g_off2[NV+1];
__device__ int   g_cur0[NR],   g_cur1[NR],   g_cur2[NV];
__device__ int   g_rank[ET];         // per-edge rank within dst bucket
__device__ int   g_srcs0[ERR], g_srcs1[EVR], g_srcs2[ERV];
__device__ float g_wdf[2*768];       // [layer][rel][head][k]
__device__ float g_M[48], g_Mc[6];   // folded edge-attr head
__device__ float g_bns[2*512];       // BN sums per layer: [req s][req sq][veh s][veh sq]
__device__ float g_prs[NR*2], g_prd[NR*2], g_pvs[NV*2], g_pvd[NV*2];
__device__ float2 g_eaM[ET];         // precomputed per-edge ea@M + Mc

__device__ __forceinline__ float lrelu(float x){ return x >= 0.f ? x : 0.2f*x; }
__device__ __forceinline__ float cleanf(float x){
  if(isnan(x)) return 0.f;
  if(isinf(x)) return x>0.f ? 3.402823466e38f : -3.402823466e38f;
  return x;
}

// packed f32x2 helpers (B300: 2x fp32 FMA throughput, PTX-only)
#define PACK_DUP(out, f) asm("mov.b64 %0, {%1, %1};" : "=l"(out) : "r"(__float_as_uint(f)))
#define FMA2(d, a, b, c) asm("fma.rn.f32x2 %0, %1, %2, %3;" : "=l"(d) : "l"(a), "l"(b), "l"(c))
#define UNPACK2(lo, hi, in) asm("mov.b64 {%0, %1}, %2;" : "=f"(lo), "=f"(hi) : "l"(in))

// BN fold: (s1,s2) for feature f of node-type `type` from raw sums
__device__ __forceinline__ void bn_fold1(const float* __restrict__ bns,
                                         const float* __restrict__ gam,
                                         const float* __restrict__ bet,
                                         int type, int goff, int f,
                                         float& s1, float& s2){
  float Nn   = type? (float)NV : (float)NR;
  float scale= type? 1.f : 0.5f;
  int base=type*256;
  float invN=1.f/Nn;
  float mu = bns[base+f]*invN;
  float var= bns[base+128+f]*invN - mu*mu;
  float rs = rsqrtf(var+1e-5f);
  float g=__ldg(&gam[goff+type*128+f]), b=__ldg(&bet[goff+type*128+f]);
  s1=scale*rs*g;
  s2=b-mu*rs*g;
}

// ---------------- setup (main stream): zero bns + counters + wdf + folded edge head -------------
#define ZB ((2*NR+NV+255)/256)
__global__ void k_setup_main(float* __restrict__ bns,
                        int* __restrict__ c0,int* __restrict__ c1,int* __restrict__ c2,
                        const float* __restrict__ Wd1,const float* __restrict__ ad1,
                        const float* __restrict__ Wd2,const float* __restrict__ ad2,
                        const float* __restrict__ Wp,const float* __restrict__ bp,
                        const float* __restrict__ Wlin,const float* __restrict__ blin,
                        float* __restrict__ wdf, float* __restrict__ M, float* __restrict__ Mc){
  int b=blockIdx.x;
  if(b>=4){
    int i=(b-4)*256+threadIdx.x;
    if(i<NR) c0[i]=0;
    else if(i<2*NR) c1[i-NR]=0;
    else if(i<2*NR+NV) c2[i-2*NR]=0;
    return;
  }
  int t=b*256+threadIdx.x;   // 0..1023
  bns[t]=0.f;
  if(t<96){
    int rel=t/32, rem=t%32, h=rem/16, k=rem%16;
    const float* w=Wd1+(size_t)rel*16*128 + k*128 + h*64;
    const float* a=ad1+rel*128+h*64;
    float s=0.f; for(int j=0;j<64;j++) s+=w[j]*a[j];
    wdf[rel*256+h*128+k]=s;
  } else if(t<864){
    int i=t-96; int rel=i/256, rem=i%256, h=rem/128, k=rem%128;
    const float* w=Wd2+(size_t)rel*128*128 + k*128 + h*64;
    const float* a=ad2+rel*128+h*64;
    float s=0.f; for(int j=0;j<64;j++) s+=w[j]*a[j];
    wdf[768+rel*256+h*128+k]=s;
  } else if(t<912){
    int q=t-864; int rel=q>>4, rem=q&15, k=rem>>1, o=rem&1;
    float s=0.f;
    for(int j=0;j<64;j++) s+=Wp[rel*512+k*64+j]*Wlin[(128+j)*2+o];
    M[q]=s;
  } else if(t<918){
    int i=t-912, rel=i>>1, o=i&1;
    float s=blin[o];
    for(int j=0;j<64;j++) s+=bp[rel*64+j]*Wlin[(128+j)*2+o];
    Mc[i]=s;
  }
}

// ---------------- side-stream CSR build: count (stores rank) -> scan -> atomic-free fill --------
__global__ void k_count3(const int* __restrict__ d0,const int* __restrict__ d1,const int* __restrict__ d2,
                         int* __restrict__ c0,int* __restrict__ c1,int* __restrict__ c2,
                         int* __restrict__ rank){
  int t=blockIdx.x*blockDim.x+threadIdx.x;
  const int Q0=ERR/4, Q1=EVR/4, Q2=ERV/4;
  int4 r;
  if(t<Q0){
    int4 d=((const int4*)d0)[t];
    r.x=atomicAdd(&c0[d.x],1); r.y=atomicAdd(&c0[d.y],1);
    r.z=atomicAdd(&c0[d.z],1); r.w=atomicAdd(&c0[d.w],1);
    ((int4*)rank)[t]=r;
  } else if(t<Q0+Q1){
    int4 d=((const int4*)d1)[t-Q0];
    r.x=atomicAdd(&c1[d.x],1); r.y=atomicAdd(&c1[d.y],1);
    r.z=atomicAdd(&c1[d.z],1); r.w=atomicAdd(&c1[d.w],1);
    ((int4*)rank)[t]=r;
  } else if(t<Q0+Q1+Q2){
    int4 d=((const int4*)d2)[t-Q0-Q1];
    r.x=atomicAdd(&c2[d.x],1); r.y=atomicAdd(&c2[d.y],1);
    r.z=atomicAdd(&c2[d.z],1); r.w=atomicAdd(&c2[d.w],1);
    ((int4*)rank)[t]=r;
  }
}
__global__ void k_scan3(const int* __restrict__ c0,int* __restrict__ o0,
                        const int* __restrict__ c1,int* __restrict__ o1,
                        const int* __restrict__ c2,int* __restrict__ o2){
  __shared__ int part[1024];
  const int* cnt; int* off; int n;
  if(blockIdx.x==0){cnt=c0;off=o0;n=NR;}
  else if(blockIdx.x==1){cnt=c1;off=o1;n=NR;}
  else {cnt=c2;off=o2;n=NV;}
  int t=threadIdx.x;
  int chunk=(n+1023)>>10;
  int lo=t*chunk, hi=min(n, lo+chunk);
  int s=0;
  for(int i=lo;i<hi;i++) s+=cnt[i];
  part[t]=s;
  __syncthreads();
  for(int d=1;d<1024;d<<=1){
    int v=(t>=d)? part[t-d]:0;
    __syncthreads();
    if(t>=d) part[t]+=v;
    __syncthreads();
  }
  int base=(t==0)?0:part[t-1];
  for(int i=lo;i<hi;i++){ int c=cnt[i]; off[i]=base; base+=c; }
  if(t==1023) off[n]=part[1023];
}
__global__ void k_fill3(const int* __restrict__ rr,const int* __restrict__ vr,const int* __restrict__ rv,
                        const int* __restrict__ o0,const int* __restrict__ o1,const int* __restrict__ o2,
                        const int* __restrict__ rank,
                        int* __restrict__ s0,int* __restrict__ s1,int* __restrict__ s2){
  int t=blockIdx.x*blockDim.x+threadIdx.x;
  const int Q0=ERR/4, Q1=EVR/4, Q2=ERV/4;
  if(t<Q0){
    int4 sr=((const int4*)rr)[t];
    int4 ds=((const int4*)(rr+ERR))[t];
    int4 rk=((const int4*)rank)[t];
    s0[__ldg(&o0[ds.x])+rk.x]=sr.x;
    s0[__ldg(&o0[ds.y])+rk.y]=sr.y;
    s0[__ldg(&o0[ds.z])+rk.z]=sr.z;
    s0[__ldg(&o0[ds.w])+rk.w]=sr.w;
  } else if(t<Q0+Q1){
    int i=t-Q0;
    int4 sr=((const int4*)vr)[i];
    int4 ds=((const int4*)(vr+EVR))[i];
    int4 rk=((const int4*)rank)[t];
    s1[__ldg(&o1[ds.x])+rk.x]=sr.x;
    s1[__ldg(&o1[ds.y])+rk.y]=sr.y;
    s1[__ldg(&o1[ds.z])+rk.z]=sr.z;
    s1[__ldg(&o1[ds.w])+rk.w]=sr.w;
  } else if(t<Q0+Q1+Q2){
    int i=t-Q0-Q1;
    int4 sr=((const int4*)rv)[i];
    int4 ds=((const int4*)(rv+ERV))[i];
    int4 rk=((const int4*)rank)[t];
    s2[__ldg(&o2[ds.x])+rk.x]=sr.x;
    s2[__ldg(&o2[ds.y])+rk.y]=sr.y;
    s2[__ldg(&o2[ds.z])+rk.z]=sr.z;
    s2[__ldg(&o2[ds.w])+rk.w]=sr.w;
  }
}

// ---------------- per-edge attr projection: eaM[e] = ea[e]@M + Mc (main stream, idle window) ----
__device__ __forceinline__ void eaM4(const float* __restrict__ ea, int i4,
                                     const float* __restrict__ M, const float* __restrict__ Mc,
                                     float2* __restrict__ eaM, int obase){
  float mm[16];
  #pragma unroll
  for(int k=0;k<16;k++) mm[k]=__ldg(&M[k]);
  float c0=__ldg(&Mc[0]), c1=__ldg(&Mc[1]);
  #pragma unroll
  for(int q=0;q<4;q++){
    int e=i4*4+q;
    float4 a0=__ldg((const float4*)(ea+(size_t)e*8));
    float4 a1=__ldg((const float4*)(ea+(size_t)e*8)+1);
    float av[8]={a0.x,a0.y,a0.z,a0.w,a1.x,a1.y,a1.z,a1.w};
    float l0=c0, l1=c1;
    #pragma unroll
    for(int k=0;k<8;k++){
      float a=cleanf(av[k]);
      l0+=a*mm[k*2]; l1+=a*mm[k*2+1];
    }
    eaM[obase+e]=make_float2(l0,l1);
  }
}
__global__ void k_eaM(const float* __restrict__ ea_rr, const float* __restrict__ ea_vr,
                      const float* __restrict__ ea_rv,
                      const float* __restrict__ M, const float* __restrict__ Mc,
                      float2* __restrict__ eaM){
  int t=blockIdx.x*blockDim.x+threadIdx.x;
  const int Q0=ERR/4, Q1=EVR/4, Q2=ERV/4;
  if(t<Q0)            eaM4(ea_rr,t,      M,   Mc,  eaM,0);
  else if(t<Q0+Q1)    eaM4(ea_vr,t-Q0,   M+16,Mc+2,eaM,ERR);
  else if(t<Q0+Q1+Q2) eaM4(ea_rv,t-Q0-Q1,M+32,Mc+4,eaM,ERR+EVR);
}

// ---------------- GEMM (f32x2): 3 relations/launch; fused es + ed; staged BN(inline fold)/clean --
template<int K, int MODE>
__global__ void k_gemm3(const float* __restrict__ Ar, const float* __restrict__ Av,
                        const float* __restrict__ W,
                        __half* __restrict__ hs0, __half* __restrict__ hs1, __half* __restrict__ hs2,
                        const float* __restrict__ as,
                        float* __restrict__ es0, float* __restrict__ es1, float* __restrict__ es2,
                        const float* __restrict__ wdf,
                        float* __restrict__ ed0, float* __restrict__ ed1, float* __restrict__ ed2,
                        const float* __restrict__ bns,
                        const float* __restrict__ gam, const float* __restrict__ bet){
  constexpr int CH = (K<32)?K:32;
  constexpr int NI = (K+31)/32;
  __shared__ float Wsh[CH*128];
  __shared__ float Ash[64*K];
  int t=threadIdx.x, warp=t>>5, lane=t&31;
  int rel=blockIdx.y;
  const float* A; __half* C; float* es; int N;
  const float* wd0=nullptr; const float* wd1=nullptr;
  float* edA=nullptr; float* edB=nullptr;
  if(rel==0){A=Ar;C=hs0;es=es0;N=NR;wd0=wdf;wd1=wdf+256;edA=ed0;edB=ed1;}
  else if(rel==1){A=Av;C=hs1;es=es1;N=NV;wd0=wdf+512;edA=ed2;}
  else {A=Ar;C=hs2;es=es2;N=NR;}
  int row0=blockIdx.x*64;
  if(row0>=N) return;
  const float* Wr = W + (size_t)rel*K*128;

  float b1[4]={0,0,0,0}, b2[4]={0,0,0,0};
  if(MODE==1){
    int type=(rel==1)?1:0;
    int fb=(t%(K/4))*4;
    #pragma unroll
    for(int q=0;q<4;q++) bn_fold1(bns,gam,bet,type,0,fb+q,b1[q],b2[q]);
  }

  for(int i=t;i<64*(K/4);i+=256){
    int r=i/(K/4), c=i%(K/4);
    if(row0+r<N){
      float4 v=((const float4*)(A+(size_t)(row0+r)*K))[c];
      if(MODE==0){v.x=cleanf(v.x);v.y=cleanf(v.y);v.z=cleanf(v.z);v.w=cleanf(v.w);}
      else {
        v.x=lrelu(v.x*b1[0]+b2[0]); v.y=lrelu(v.y*b1[1]+b2[1]);
        v.z=lrelu(v.z*b1[2]+b2[2]); v.w=lrelu(v.w*b1[3]+b2[3]);
      }
      ((float4*)Ash)[i]=v;
    }
  }

  unsigned long long acc[8][2];
  #pragma unroll
  for(int r=0;r<8;r++){acc[r][0]=0ull;acc[r][1]=0ull;}

  for(int kc=0;kc<K;kc+=CH){
    __syncthreads();
    {
      const float4* Wg=(const float4*)(Wr+(size_t)kc*128);
      float4* Ws4=(float4*)Wsh;
      for(int i=t;i<CH*32;i+=256) Ws4[i]=Wg[i];
    }
    __syncthreads();
    const ulonglong2* W2=(const ulonglong2*)Wsh;
    #pragma unroll
    for(int k4=0;k4<CH/4;k4++){
      ulonglong2 w0=W2[(k4*4+0)*32+lane];
      ulonglong2 w1=W2[(k4*4+1)*32+lane];
      ulonglong2 w2=W2[(k4*4+2)*32+lane];
      ulonglong2 w3=W2[(k4*4+3)*32+lane];
      #pragma unroll
      for(int r=0;r<8;r++){
        float4 a=*(const float4*)(Ash + (warp*8+r)*K + kc + k4*4);
        unsigned long long ax,ay,az,aw;
        PACK_DUP(ax,a.x); PACK_DUP(ay,a.y); PACK_DUP(az,a.z); PACK_DUP(aw,a.w);
        FMA2(acc[r][0],ax,w0.x,acc[r][0]); FMA2(acc[r][1],ax,w0.y,acc[r][1]);
        FMA2(acc[r][0],ay,w1.x,acc[r][0]); FMA2(acc[r][1],ay,w1.y,acc[r][1]);
        FMA2(acc[r][0],az,w2.x,acc[r][0]); FMA2(acc[r][1],az,w2.y,acc[r][1]);
        FMA2(acc[r][0],aw,w3.x,acc[r][0]); FMA2(acc[r][1],aw,w3.y,acc[r][1]);
      }
    }
  }

  float4 av=__ldg((const float4*)(as+rel*128)+lane);
  float wA0[NI],wA1[NI],wB0[NI],wB1[NI];
  if(edA){
    #pragma unroll
    for(int i=0;i<NI;i++){
      int k=lane+32*i;
      wA0[i]=(k<K)?__ldg(&wd0[k]):0.f;
      wA1[i]=(k<K)?__ldg(&wd0[128+k]):0.f;
      if(edB){ wB0[i]=(k<K)?__ldg(&wd1[k]):0.f; wB1[i]=(k<K)?__ldg(&wd1[128+k]):0.f; }
    }
  }
  #pragma unroll
  for(int r=0;r<8;r++){
    int row=row0+warp*8+r;
    if(row>=N) continue;
    float4 o;
    UNPACK2(o.x,o.y,acc[r][0]);
    UNPACK2(o.z,o.w,acc[r][1]);
    union { __half2 h[2]; uint2 u; } cv;
    cv.h[0]=__floats2half2_rn(o.x,o.y);
    cv.h[1]=__floats2half2_rn(o.z,o.w);
    ((uint2*)C)[row*32+lane]=cv.u;
    float s=o.x*av.x+o.y*av.y+o.z*av.z+o.w*av.w;
    #pragma unroll
    for(int off=8;off>=1;off>>=1) s+=__shfl_xor_sync(0xffffffffu,s,off,16);
    if(lane==0)  es[row*2]=s;
    if(lane==16) es[row*2+1]=s;
    if(edA){
      float s0=0.f,s1=0.f,s2=0.f,s3=0.f;
      #pragma unroll
      for(int i=0;i<NI;i++){
        int k=lane+32*i;
        if(k<K){
          float xv=Ash[(warp*8+r)*K+k];
          s0+=xv*wA0[i]; s1+=xv*wA1[i];
          if(edB){ s2+=xv*wB0[i]; s3+=xv*wB1[i]; }
        }
      }
      #pragma unroll
      for(int off=16;off>=1;off>>=1){
        s0+=__shfl_xor_sync(0xffffffffu,s0,off);
        s1+=__shfl_xor_sync(0xffffffffu,s1,off);
        if(edB){ s2+=__shfl_xor_sync(0xffffffffu,s2,off); s3+=__shfl_xor_sync(0xffffffffu,s3,off); }
      }
      if(lane==0){
        edA[row*2]=s0; edA[row*2+1]=s1;
        if(edB){ edB[row*2]=s2; edB[row*2+1]=s3; }
      }
    }
  }
}

// ---------------- softmax-aggregate one relation for node w (warp-collective, fp16 hs) ----------
__device__ __forceinline__ float4 hgather(const __half* __restrict__ hs, int sj, int lane){
  uint2 hv=__ldg((const uint2*)hs + (size_t)sj*32 + lane);
  __half2 a01=*(__half2*)&hv.x, a23=*(__half2*)&hv.y;
  float2 f01=__half22float2(a01), f23=__half22float2(a23);
  return make_float4(f01.x,f01.y,f23.x,f23.y);
}

__device__ __forceinline__ float4 agg_rel(
    const int* __restrict__ off, const int* __restrict__ srcs,
    const float* __restrict__ es, const float* __restrict__ ed,
    const __half* __restrict__ hs, int w, int lane, bool h1)
{
  float4 acc=make_float4(0.f,0.f,0.f,0.f);
  int a0=off[w], deg=off[w+1]-a0;
  if(deg==0) return acc;
  float ed0=ed[w*2], ed1=ed[w*2+1];
  if(deg<=128){
    int nc=(deg+31)>>5;
    int   sreg[4];
    float e0[4], e1[4];
    float m0=-1e30f, m1=-1e30f;
    #pragma unroll
    for(int c=0;c<4;c++){
      e0[c]=-1e30f; e1[c]=-1e30f; sreg[c]=0;
      if(c<nc){
        int i=c*32+lane;
        if(i<deg){
          int s=__ldg(&srcs[a0+i]); sreg[c]=s;
          float2 ev=__ldg((const float2*)(es)+s);
          e0[c]=lrelu(ev.x+ed0); e1[c]=lrelu(ev.y+ed1);
          m0=fmaxf(m0,e0[c]); m1=fmaxf(m1,e1[c]);
        }
      }
    }
    #pragma unroll
    for(int o=16;o>=1;o>>=1){
      m0=fmaxf(m0,__shfl_xor_sync(0xffffffffu,m0,o));
      m1=fmaxf(m1,__shfl_xor_sync(0xffffffffu,m1,o));
    }
    float s0=0.f, s1=0.f;
    #pragma unroll
    for(int c=0;c<4;c++){
      e0[c]=__expf(e0[c]-m0);
      e1[c]=__expf(e1[c]-m1);
      s0+=e0[c]; s1+=e1[c];
    }
    #pragma unroll
    for(int o=16;o>=1;o>>=1){
      s0+=__shfl_xor_sync(0xffffffffu,s0,o);
      s1+=__shfl_xor_sync(0xffffffffu,s1,o);
    }
    float inv=1.f/(h1?s1:s0);
    #pragma unroll
    for(int c=0;c<4;c++){
      if(c>=nc) break;
      int n=min(32,deg-c*32);
      for(int j=0;j<n;j++){
        int   sj=__shfl_sync(0xffffffffu,sreg[c],j);
        float aa=__shfl_sync(0xffffffffu,e0[c],j);
        float ab=__shfl_sync(0xffffffffu,e1[c],j);
        float al=(h1?ab:aa)*inv;
        float4 h=hgather(hs,sj,lane);
        acc.x+=h.x*al; acc.y+=h.y*al; acc.z+=h.z*al; acc.w+=h.w*al;
      }
    }
  } else {
    float m0=-1e30f, m1=-1e30f;
    for(int i=lane;i<deg;i+=32){
      int s=__ldg(&srcs[a0+i]);
      float2 ev=__ldg((const float2*)(es)+s);
      m0=fmaxf(m0,lrelu(ev.x+ed0)); m1=fmaxf(m1,lrelu(ev.y+ed1));
    }
    for(int o=16;o>=1;o>>=1){
      m0=fmaxf(m0,__shfl_xor_sync(0xffffffffu,m0,o));
      m1=fmaxf(m1,__shfl_xor_sync(0xffffffffu,m1,o));
    }
    float s0=0.f, s1=0.f;
    for(int i=lane;i<deg;i+=32){
      int s=__ldg(&srcs[a0+i]);
      float2 ev=__ldg((const float2*)(es)+s);
      s0+=__expf(lrelu(ev.x+ed0)-m0);
      s1+=__expf(lrelu(ev.y+ed1)-m1);
    }
    for(int o=16;o>=1;o>>=1){
      s0+=__shfl_xor_sync(0xffffffffu,s0,o);
      s1+=__shfl_xor_sync(0xffffffffu,s1,o);
    }
    float inv=1.f/(h1?s1:s0);
    for(int base=0;base<deg;base+=32){
      int n=min(32,deg-base);
      int sv=0; float ev0=0.f, ev1=0.f;
      if(lane<n){
        sv=__ldg(&srcs[a0+base+lane]);
        float2 ev=__ldg((const float2*)(es)+sv);
        ev0=__expf(lrelu(ev.x+ed0)-m0);
        ev1=__expf(lrelu(ev.y+ed1)-m1);
      }
      for(int j=0;j<n;j++){
        int   sj=__shfl_sync(0xffffffffu,sv,j);
        float aa=__shfl_sync(0xffffffffu,ev0,j);
        float ab=__shfl_sync(0xffffffffu,ev1,j);
        float al=(h1?ab:aa)*inv;
        float4 h=hgather(hs,sj,lane);
        acc.x+=h.x*al; acc.y+=h.y*al; acc.z+=h.z*al; acc.w+=h.w*al;
      }
    }
  }
  return acc;
}

// agg + bias + fused BN statistics. 1 node/warp; 128-thread blocks (4 nodes) for
// finer load balance (cross-CTA spread shrinks with smaller Sdeg variance/block).
// veh blocks first (3x longer).
__global__ void k_agg_all(const int* __restrict__ off0,const int* __restrict__ s0,
                          const float* __restrict__ es0,const float* __restrict__ ed0,
                          const __half* __restrict__ hs0,
                          const int* __restrict__ off1,const int* __restrict__ s1,
                          const float* __restrict__ es1,const float* __restrict__ ed1,
                          const __half* __restrict__ hs1,
                          const int* __restrict__ off2,const int* __restrict__ s2,
                          const float* __restrict__ es2,const float* __restrict__ ed2,
                          const __half* __restrict__ hs2,
                          const float* __restrict__ bs,
                          float* __restrict__ accr, float* __restrict__ accv,
                          float* __restrict__ bns){
  __shared__ float s_sum[128], s_sq[128];
  int t=threadIdx.x, warp=t>>5, lane=t&31;
  bool h1=lane>=16;
  s_sum[t]=0.f; s_sq[t]=0.f;
  __syncthreads();
  bool isveh = blockIdx.x<(NV/4);
  float4 v;
  if(isveh){
    int w=blockIdx.x*4+warp;
    float4 b0=__ldg((const float4*)(bs+256)+lane);
    float4 a=agg_rel(off2,s2,es2,ed2,hs2,w,lane,h1);
    float4 o;
    o.x=b0.x+a.x; o.y=b0.y+a.y; o.z=b0.z+a.z; o.w=b0.w+a.w;
    ((float4*)(accv+(size_t)w*128))[lane]=o;
    v=o;
  } else {
    int w=(blockIdx.x-(NV/4))*4+warp;
    float4 b0=__ldg((const float4*)bs+lane);
    float4 b1=__ldg((const float4*)(bs+128)+lane);
    float4 a=agg_rel(off0,s0,es0,ed0,hs0,w,lane,h1);
    float4 b=agg_rel(off1,s1,es1,ed1,hs1,w,lane,h1);
    float4 o;
    o.x=b0.x+b1.x+a.x+b.x; o.y=b0.y+b1.y+a.y+b.y;
    o.z=b0.z+b1.z+a.z+b.z; o.w=b0.w+b1.w+a.w+b.w;
    ((float4*)(accr+(size_t)w*128))[lane]=o;
    v.x=0.5f*o.x; v.y=0.5f*o.y; v.z=0.5f*o.z; v.w=0.5f*o.w;
  }
  int f=lane*4;
  atomicAdd(&s_sum[f+0],v.x); atomicAdd(&s_sum[f+1],v.y);
  atomicAdd(&s_sum[f+2],v.z); atomicAdd(&s_sum[f+3],v.w);
  atomicAdd(&s_sq[f+0],v.x*v.x); atomicAdd(&s_sq[f+1],v.y*v.y);
  atomicAdd(&s_sq[f+2],v.z*v.z); atomicAdd(&s_sq[f+3],v.w*v.w);
  __syncthreads();
  int base=isveh?256:0;
  atomicAdd(&bns[base+t], s_sum[t]);
  atomicAdd(&bns[base+128+t], s_sq[t]);
}

// ---------------- final head: node projections (inline layer-2 BN fold) ----------------
__global__ void k_proj4(const float* __restrict__ accr, const float* __restrict__ accv,
                        const float* __restrict__ bns,
                        const float* __restrict__ gam, const float* __restrict__ bet,
                        const float* __restrict__ Wlin,
                        float* __restrict__ prs, float* __restrict__ prd,
                        float* __restrict__ pvs, float* __restrict__ pvd){
  int gid=blockIdx.x*blockDim.x+threadIdx.x;
  int w=gid>>5, lane=gid&31;
  const float* X; float* P; int base; int idx; int type;
  if(w<NR){X=accr;P=prs;base=0;idx=w;type=0;}
  else if(w<2*NR){X=accr;P=prd;base=192;idx=w-NR;type=0;}
  else if(w<2*NR+NV){X=accv;P=pvs;base=0;idx=w-2*NR;type=1;}
  else if(w<2*NR+2*NV){X=accv;P=pvd;base=192;idx=w-2*NR-NV;type=1;}
  else return;
  float4 x=__ldg((const float4*)(X+(size_t)idx*FEA)+lane);
  float s1[4],s2[4];
  #pragma unroll
  for(int q=0;q<4;q++) bn_fold1(bns,gam,bet,type,256,lane*4+q,s1[q],s2[q]);
  x.x=lrelu(x.x*s1[0]+s2[0]); x.y=lrelu(x.y*s1[1]+s2[1]);
  x.z=lrelu(x.z*s1[2]+s2[2]); x.w=lrelu(x.w*s1[3]+s2[3]);
  const float* wr=Wlin+(base+lane*4)*2;
  float4 wa=__ldg((const float4*)wr);
  float4 wb=__ldg((const float4*)wr+1);
  float p0=x.x*wa.x + x.y*wa.z + x.z*wb.x + x.w*wb.z;
  float p1=x.x*wa.y + x.y*wa.w + x.z*wb.y + x.w*wb.w;
  for(int o=16;o>=1;o>>=1){
    p0+=__shfl_xor_sync(0xffffffffu,p0,o);
    p1+=__shfl_xor_sync(0xffffffffu,p1,o);
  }
  if(lane==0){ P[idx*2]=p0; P[idx*2+1]=p1; }
}

// ---------------- per-edge output (4 edges/thread; uses precomputed eaM) ----------------
__device__ __forceinline__ void edge4(const int* __restrict__ ei, int E, int i4,
                                      const float* __restrict__ ps, const float* __restrict__ pd,
                                      const float2* __restrict__ eaM,
                                      float* __restrict__ out, int obase){
  int4 sr=((const int4*)ei)[i4];
  int4 ds=((const int4*)(ei+E))[i4];
  int ss[4]={sr.x,sr.y,sr.z,sr.w};
  int dd[4]={ds.x,ds.y,ds.z,ds.w};
  float2 pse[4], pde[4], em[4];
  #pragma unroll
  for(int q=0;q<4;q++){
    pse[q]=__ldg((const float2*)ps+ss[q]);
    pde[q]=__ldg((const float2*)pd+dd[q]);
    em[q]=__ldg(&eaM[obase+i4*4+q]);
  }
  #pragma unroll
  for(int q=0;q<4;q++){
    int e=i4*4+q;
    float l0=pse[q].x+pde[q].x+em[q].x;
    float l1=pse[q].y+pde[q].y+em[q].y;
    float mx=fmaxf(l0,l1);
    float e0=__expf(l0-mx), e1=__expf(l1-mx);
    float inv=1.f/(e0+e1);
    out[(size_t)(obase+e)*2]=e0*inv; out[(size_t)(obase+e)*2+1]=e1*inv;
  }
}

__global__ void k_edgeout_all(const int* __restrict__ ei_rr,
                              const int* __restrict__ ei_vr,
                              const int* __restrict__ ei_rv,
                              const float* __restrict__ prs, const float* __restrict__ prd,
                              const float* __restrict__ pvs, const float* __restrict__ pvd,
                              const float2* __restrict__ eaM,
                              float* __restrict__ out){
  int t=blockIdx.x*blockDim.x+threadIdx.x;
  const int Q0=ERR/4, Q1=EVR/4, Q2=ERV/4;
  if(t<Q0)            edge4(ei_rr,ERR,t,      prs,prd,eaM,out,0);
  else if(t<Q0+Q1)    edge4(ei_vr,EVR,t-Q0,   pvs,prd,eaM,out,ERR);
  else if(t<Q0+Q1+Q2) edge4(ei_rv,ERV,t-Q0-Q1,prs,pvd,eaM,out,ERR+EVR);
}

// ---------------- host ----------------
#define SYM(var, sym) do{ void* _p; cudaGetSymbolAddress(&_p, sym); var=(decltype(var))_p; }while(0)

extern "C" void kernel_launch(void* const* d_in, const int* in_sizes, int n_in,
                              void* d_out, int out_size){
  (void)in_sizes; (void)n_in; (void)out_size;
  const float* x_req=(const float*)d_in[0];
  const float* x_veh=(const float*)d_in[1];
  const int*   ei_rr=(const int*)d_in[2];
  const int*   ei_vr=(const int*)d_in[3];
  const int*   ei_rv=(const int*)d_in[4];
  const float* ea_rr=(const float*)d_in[5];
  const float* ea_vr=(const float*)d_in[6];
  const float* ea_rv=(const float*)d_in[7];
  const float* Wsrc1=(const float*)d_in[8];
  const float* Wdst1=(const float*)d_in[9];
  const float* asrc1=(const float*)d_in[10];
  const float* adst1=(const float*)d_in[11];
  const float* bias1=(const float*)d_in[12];
  const float* Wsrc2=(const float*)d_in[13];
  const float* Wdst2=(const float*)d_in[14];
  const float* asrc2=(const float*)d_in[15];
  const float* adst2=(const float*)d_in[16];
  const float* bias2=(const float*)d_in[17];
  const float* bn_gamma=(const float*)d_in[18];
  const float* bn_beta =(const float*)d_in[19];
  const float* Wp  =(const float*)d_in[20];
  const float* bp  =(const float*)d_in[21];
  const float* Wlin=(const float*)d_in[22];
  const float* blin=(const float*)d_in[23];
  float* out=(float*)d_out;

  __half *hs0,*hs1,*hs2;
  float *accr,*accv;
  float *es0,*es1,*es2,*ed0,*ed1,*ed2,*wdf,*M,*Mc,*bns,*prs,*prd,*pvs,*pvd;
  float2 *eaM;
  int *off0,*off1,*off2,*cur0,*cur1,*cur2,*srcs0,*srcs1,*srcs2,*rank;
  SYM(hs0,g_hs0); SYM(hs1,g_hs1); SYM(hs2,g_hs2);
  SYM(accr,g_accr); SYM(accv,g_accv);
  SYM(es0,g_es0); SYM(es1,g_es1); SYM(es2,g_es2);
  SYM(ed0,g_ed0); SYM(ed1,g_ed1); SYM(ed2,g_ed2);
  SYM(off0,g_off0); SYM(off1,g_off1); SYM(off2,g_off2);
  SYM(cur0,g_cur0); SYM(cur1,g_cur1); SYM(cur2,g_cur2);
  SYM(srcs0,g_srcs0); SYM(srcs1,g_srcs1); SYM(srcs2,g_srcs2); SYM(rank,g_rank);
  SYM(wdf,g_wdf); SYM(M,g_M); SYM(Mc,g_Mc); SYM(bns,g_bns);
  SYM(prs,g_prs); SYM(prd,g_prd); SYM(pvs,g_pvs); SYM(pvd,g_pvd);
  SYM(eaM,g_eaM);

  // fork a side stream for the CSR build (graph-capturable event fork/join).
  // stream/event objects are host-side; intentionally not destroyed (capture
  // forbids destroying in-capture streams; kernel_launch runs O(1) times).
  cudaStream_t sidest;
  cudaEvent_t evSetup, evJoin;
  cudaStreamCreateWithFlags(&sidest, cudaStreamNonBlocking);
  cudaEventCreateWithFlags(&evSetup, cudaEventDisableTiming);
  cudaEventCreateWithFlags(&evJoin, cudaEventDisableTiming);

  // ---- main stream: setup (zeros counters + bns, computes wdf/M/Mc) ----
  k_setup_main<<<4+ZB,256>>>(bns,cur0,cur1,cur2,Wdst1,adst1,Wdst2,adst2,
                             Wp,bp,Wlin,blin,wdf,M,Mc);
  cudaEventRecord(evSetup, 0);

  // ---- side stream: CSR build (count stores rank; fill atomic-free) ----
  cudaStreamWaitEvent(sidest, evSetup, 0);
  k_count3<<<(ET/4+255)/256,256,0,sidest>>>(ei_rr+ERR,ei_vr+EVR,ei_rv+ERV,
                                            cur0,cur1,cur2,rank);
  k_scan3<<<3,1024,0,sidest>>>(cur0,off0,cur1,off1,cur2,off2);
  k_fill3<<<(ET/4+255)/256,256,0,sidest>>>(ei_rr,ei_vr,ei_rv,off0,off1,off2,rank,
                                           srcs0,srcs1,srcs2);
  cudaEventRecord(evJoin, sidest);

  // ---- main stream: gemm L0 + eaM precompute (independent of CSR) ----
  {
    dim3 grid((NR+63)/64,3);
    k_gemm3<16,0><<<grid,256>>>(x_req,x_veh,Wsrc1,hs0,hs1,hs2,asrc1,es0,es1,es2,
                                wdf,ed0,ed1,ed2,nullptr,nullptr,nullptr);
  }
  k_eaM<<<(ET/4+255)/256,256>>>(ea_rr,ea_vr,ea_rv,M,Mc,eaM);

  // join: agg needs CSR + gemm outputs
  cudaStreamWaitEvent(0, evJoin, 0);

  // ---- layer 0 agg ----
  k_agg_all<<<NR/4+NV/4,128>>>(off0,srcs0,es0,ed0,hs0, off1,srcs1,es1,ed1,hs1,
                               off2,srcs2,es2,ed2,hs2, bias1,accr,accv,bns);
  // ---- layer 1 (BN-0 fold inlined into A staging) ----
  {
    dim3 grid((NR+63)/64,3);
    k_gemm3<128,1><<<grid,256>>>(accr,accv,Wsrc2,hs0,hs1,hs2,asrc2,es0,es1,es2,
                                 wdf+768,ed0,ed1,ed2,bns,bn_gamma,bn_beta);
  }
  k_agg_all<<<NR/4+NV/4,128>>>(off0,srcs0,es0,ed0,hs0, off1,srcs1,es1,ed1,hs1,
                               off2,srcs2,es2,ed2,hs2, bias2,accr,accv,bns+512);

  // ---- final per-edge head (BN-1 fold inlined into proj; edgeout uses eaM) ----
  k_proj4<<<((2*NR+2*NV)*32+255)/256,256>>>(accr,accv,bns+512,bn_gamma,bn_beta,
                                            Wlin,prs,prd,pvs,pvd);
  k_edgeout_all<<<(ET/4+255)/256,256>>>(ei_rr,ei_vr,ei_rv,
                                        prs,prd,pvs,pvd,eaM,out);
}